// round 11
// baseline (speedup 1.0000x reference)
#include <cuda_runtime.h>
#include <cuda_fp16.h>

// Problem shape (fixed by setup_inputs): B=4, N=100000, C=32, E=1600000
#define NMAX 100000
#define EMAX 1600000
#define NB   4
#define CH   32
#define BC   128            // NB*CH channels per node
#define CAP  64             // fixed adjacency capacity (Poisson(16): P(deg>64)~1e-20)
#define NPART 1024

// Scratch (device globals — zero-initialized at module load; every invocation
// restores them to zero, keeping graph replays deterministic).
// g_Dh has NMAX+1 rows: row NMAX is an all-zero sentinel (never written) used
// to pad gather loops without divergence.
__device__ __half   g_Dh[(size_t)(NMAX + 1) * BC];  // 25.6 MB + 256B sentinel
__device__ int      g_cur[NMAX];                    // per-node fill counter
__device__ int      g_adj[(size_t)NMAX * CAP];      // 25.6 MB fixed-slot adjacency
__device__ float    g_part[NPART];
__device__ unsigned g_done;

// ---------------- fused prep: diff (blocks [0,db)) + scatter (blocks [db,..))
__global__ void __launch_bounds__(256) k_prep(const float* __restrict__ pred,
                                              const float* __restrict__ tgt,
                                              const int* __restrict__ src,
                                              const int* __restrict__ dst,
                                              int n, int e, int db) {
    if ((int)blockIdx.x < db) {
        int t = blockIdx.x * 256 + threadIdx.x;      // 0 .. n*16-1
        if (t >= n * 16) return;
        int node = t >> 4;
        int s    = t & 15;           // uint4 slot in row (8 halves)
        int b    = s >> 2;
        int c    = (s & 3) * 8;
        const float4* P = (const float4*)(pred + (size_t)b * n * CH
                                               + (size_t)node * CH + c);
        const float4* T = (const float4*)(tgt  + (size_t)b * n * CH
                                               + (size_t)node * CH + c);
        float4 p0 = __ldcs(P);
        float4 p1 = __ldcs(P + 1);
        float4 t0 = __ldcs(T);
        float4 t1 = __ldcs(T + 1);
        uint4 o;
        *(__half2*)&o.x = __floats2half2_rn(p0.x - t0.x, p0.y - t0.y);
        *(__half2*)&o.y = __floats2half2_rn(p0.z - t0.z, p0.w - t0.w);
        *(__half2*)&o.z = __floats2half2_rn(p1.x - t1.x, p1.y - t1.y);
        *(__half2*)&o.w = __floats2half2_rn(p1.z - t1.z, p1.w - t1.w);
        ((uint4*)g_Dh)[(size_t)node * 16 + s] = o;
    } else {
        int i = (blockIdx.x - db) * 256 + threadIdx.x;
        if (i < e) {
            int d = __ldcs(dst + i);
            int p = atomicAdd(&g_cur[d], 1);
            if (p < CAP) g_adj[(size_t)d * CAP + p] = __ldcs(src + i);
        }
    }
}

// ---------------- main: 1 warp per node, fp16 rows (256B = 16 lanes x uint4)
// lane L: channel-quad cl=L&15; lane-group grp=L>>4 handles neighbors k+grp.
// SMALL BLOCKS (64 thr = 2 warps): Poisson-degree tail imbalance inflates a
// block's lifetime by E[max of W warps]/E[deg]; W=2 costs ~1.1x vs ~1.4x at
// W=8, and retired blocks free their slot for CLC backfill immediately.
__global__ void __launch_bounds__(64, 32) k_main(int n, float* __restrict__ out,
                                                 double invcnt) {
    int gtid = blockIdx.x * blockDim.x + threadIdx.x;
    int wid  = gtid >> 5;        // node id
    int lane = gtid & 31;
    int cl   = lane & 15;
    int grp  = lane >> 4;

    float s_local = 0.f;
    if (wid < n) {
        int deg = g_cur[wid];
        if (deg > CAP) deg = CAP;
        if (deg > 0) {
            const int* __restrict__ adj = g_adj + (size_t)wid * CAP;
            const uint4* __restrict__ D = (const uint4*)g_Dh;  // 16 uint4/row
            int degP = (deg + 1) & ~1;
            __half2 h0 = __half2half2(__ushort_as_half(0));
            __half2 h1 = h0, h2 = h0, h3 = h0;
            #pragma unroll 4
            for (int k = grp; k < degP; k += 2) {
                int j = (k < deg) ? __ldg(adj + k) : n;   // n = zero sentinel
                uint4 x = D[(size_t)j * 16 + cl];
                h0 = __hadd2(h0, *(__half2*)&x.x);
                h1 = __hadd2(h1, *(__half2*)&x.y);
                h2 = __hadd2(h2, *(__half2*)&x.z);
                h3 = __hadd2(h3, *(__half2*)&x.w);
            }
            // combine neighbor-groups (lanes L and L^16 share channels)
            {
                unsigned u0 = *(unsigned*)&h0, u1 = *(unsigned*)&h1;
                unsigned u2 = *(unsigned*)&h2, u3 = *(unsigned*)&h3;
                unsigned v0 = __shfl_xor_sync(0xffffffffu, u0, 16);
                unsigned v1 = __shfl_xor_sync(0xffffffffu, u1, 16);
                unsigned v2 = __shfl_xor_sync(0xffffffffu, u2, 16);
                unsigned v3 = __shfl_xor_sync(0xffffffffu, u3, 16);
                h0 = __hadd2(h0, *(__half2*)&v0);
                h1 = __hadd2(h1, *(__half2*)&v1);
                h2 = __hadd2(h2, *(__half2*)&v2);
                h3 = __hadd2(h3, *(__half2*)&v3);
            }

            uint4 myraw = ((const uint4*)g_Dh)[(size_t)wid * 16 + cl];
            float inv = 1.0f / (float)deg;
            float2 a0 = __half22float2(h0);
            float2 a1 = __half22float2(h1);
            float2 a2 = __half22float2(h2);
            float2 a3 = __half22float2(h3);
            float2 m0 = __half22float2(*(__half2*)&myraw.x);
            float2 m1 = __half22float2(*(__half2*)&myraw.y);
            float2 m2 = __half22float2(*(__half2*)&myraw.z);
            float2 m3 = __half22float2(*(__half2*)&myraw.w);
            s_local = fabsf(m0.x - a0.x * inv) + fabsf(m0.y - a0.y * inv)
                    + fabsf(m1.x - a1.x * inv) + fabsf(m1.y - a1.y * inv)
                    + fabsf(m2.x - a2.x * inv) + fabsf(m2.y - a2.y * inv)
                    + fabsf(m3.x - a3.x * inv) + fabsf(m3.y - a3.y * inv);
            s_local *= 0.5f;   // both lane-groups computed identical terms
        }
    }
    // warp reduce -> per-warp atomic into partial slots
    #pragma unroll
    for (int d = 16; d; d >>= 1)
        s_local += __shfl_xor_sync(0xffffffffu, s_local, d);
    if (lane == 0 && s_local != 0.f)
        atomicAdd(&g_part[blockIdx.x & (NPART - 1)], s_local);

    // ---- epilogue: this block resets its own 2 nodes' counters (coalesced,
    // staggered in time across blocks; no prologue burst — see R5 lesson) ----
    {
        int i = blockIdx.x * 2 + threadIdx.x;
        if (threadIdx.x < 2 && i < n) g_cur[i] = 0;
    }

    // ---- last finishing block reduces the partials, then resets them ----
    __shared__ bool is_last;
    __threadfence();
    if (threadIdx.x == 0)
        is_last = (atomicAdd(&g_done, 1u) == gridDim.x - 1);
    __syncthreads();
    if (is_last) {
        int t = threadIdx.x;                       // 64 threads
        double s = 0.0;
        #pragma unroll
        for (int i = 0; i < NPART / 64; i++) {
            int idx = t + i * 64;
            s += (double)__ldcg(&g_part[idx]);
            g_part[idx] = 0.f;                     // restore for next invocation
        }
        #pragma unroll
        for (int d = 16; d; d >>= 1) s += __shfl_down_sync(0xffffffffu, s, d);
        __shared__ double sh[2];
        if ((t & 31) == 0) sh[t >> 5] = s;
        __syncthreads();
        if (t == 0) {
            out[0] = (float)((sh[0] + sh[1]) * invcnt);
            g_done = 0u;                           // restore for next invocation
        }
    }
}

extern "C" void kernel_launch(void* const* d_in, const int* in_sizes, int n_in,
                              void* d_out, int out_size) {
    const float* pred = (const float*)d_in[0];
    const float* tgt  = (const float*)d_in[1];
    const int*   esrc = (const int*)d_in[2];
    const int*   edst = (const int*)d_in[3];

    long long total = in_sizes[0];          // B*N*C
    int n = (int)(total / BC);              // 100000
    int e = in_sizes[2];                    // 1600000
    if (n > NMAX) n = NMAX;
    if (e > EMAX) e = EMAX;

    int db = (n * 16 + 255) / 256;          // diff blocks (8 ch/thread)
    int sb = (e + 255) / 256;               // scatter blocks
    k_prep<<<db + sb, 256>>>(pred, tgt, esrc, edst, n, e, db);

    int blocks = (n + 1) / 2;               // 2 warps/block, 1 warp/node
    k_main<<<blocks, 64>>>(n, (float*)d_out, 1.0 / (double)total);
}

// round 13
// speedup vs baseline: 1.0288x; 1.0288x over previous
#include <cuda_runtime.h>
#include <cuda_fp16.h>

// Problem shape (fixed by setup_inputs): B=4, N=100000, C=32, E=1600000
#define NMAX 100000
#define EMAX 1600000
#define NB   4
#define CH   32
#define BC   128            // NB*CH channels per node
#define CAP  64             // fixed adjacency capacity (Poisson(16): P(deg>64)~1e-20)
#define NPART 1024

// Scratch (device globals — zero-initialized at module load; every invocation
// restores them to zero, keeping graph replays deterministic).
// g_Dh has NMAX+1 rows: row NMAX is an all-zero sentinel (never written) used
// to pad gather loops without divergence.
__device__ __half   g_Dh[(size_t)(NMAX + 1) * BC];  // 25.6 MB + 256B sentinel
__device__ int      g_cur[NMAX];                    // per-node fill counter
__device__ int      g_adj[(size_t)NMAX * CAP];      // 25.6 MB fixed-slot adjacency
__device__ float    g_part[NPART];
__device__ unsigned g_done;

// ---- L2 eviction-priority via cache-policy register (works for all widths;
// the bare .L2::evict_last qualifier is v8.b32-only on sm_103a ptxas).
// Keeps D/adj resident against the 128MB pred/target stream (ld.cs). ----
__device__ __forceinline__ unsigned long long mk_evict_last() {
    unsigned long long pol;
    asm("createpolicy.fractional.L2::evict_last.b64 %0, 1.0;" : "=l"(pol));
    return pol;
}
__device__ __forceinline__ uint4 ldg_el(const uint4* p, unsigned long long pol) {
    uint4 v;
    asm("ld.global.L2::cache_hint.v4.u32 {%0,%1,%2,%3}, [%4], %5;"
        : "=r"(v.x), "=r"(v.y), "=r"(v.z), "=r"(v.w) : "l"(p), "l"(pol));
    return v;
}
__device__ __forceinline__ int ldg_el_i(const int* p, unsigned long long pol) {
    int v;
    asm("ld.global.L2::cache_hint.s32 %0, [%1], %2;" : "=r"(v) : "l"(p), "l"(pol));
    return v;
}
__device__ __forceinline__ void stg_el(uint4* p, uint4 v, unsigned long long pol) {
    asm volatile("st.global.L2::cache_hint.v4.u32 [%0], {%1,%2,%3,%4}, %5;"
                 :: "l"(p), "r"(v.x), "r"(v.y), "r"(v.z), "r"(v.w), "l"(pol));
}
__device__ __forceinline__ void stg_el_i(int* p, int v, unsigned long long pol) {
    asm volatile("st.global.L2::cache_hint.s32 [%0], %1, %2;"
                 :: "l"(p), "r"(v), "l"(pol));
}

// ---------------- fused prep: diff (blocks [0,db)) + scatter (blocks [db,..))
__global__ void __launch_bounds__(256) k_prep(const float* __restrict__ pred,
                                              const float* __restrict__ tgt,
                                              const int* __restrict__ src,
                                              const int* __restrict__ dst,
                                              int n, int e, int db) {
    unsigned long long pol = mk_evict_last();
    if ((int)blockIdx.x < db) {
        int t = blockIdx.x * 256 + threadIdx.x;      // 0 .. n*16-1
        if (t >= n * 16) return;
        int node = t >> 4;
        int s    = t & 15;           // uint4 slot in row (8 halves)
        int b    = s >> 2;
        int c    = (s & 3) * 8;
        const float4* P = (const float4*)(pred + (size_t)b * n * CH
                                               + (size_t)node * CH + c);
        const float4* T = (const float4*)(tgt  + (size_t)b * n * CH
                                               + (size_t)node * CH + c);
        float4 p0 = __ldcs(P);
        float4 p1 = __ldcs(P + 1);
        float4 t0 = __ldcs(T);
        float4 t1 = __ldcs(T + 1);
        uint4 o;
        *(__half2*)&o.x = __floats2half2_rn(p0.x - t0.x, p0.y - t0.y);
        *(__half2*)&o.y = __floats2half2_rn(p0.z - t0.z, p0.w - t0.w);
        *(__half2*)&o.z = __floats2half2_rn(p1.x - t1.x, p1.y - t1.y);
        *(__half2*)&o.w = __floats2half2_rn(p1.z - t1.z, p1.w - t1.w);
        stg_el((uint4*)g_Dh + (size_t)node * 16 + s, o, pol);
    } else {
        int i = (blockIdx.x - db) * 256 + threadIdx.x;
        if (i < e) {
            int d = __ldcs(dst + i);
            int p = atomicAdd(&g_cur[d], 1);
            if (p < CAP)
                stg_el_i(&g_adj[(size_t)d * CAP + p], __ldcs(src + i), pol);
        }
    }
}

// ---------------- main: 1 warp per node, fp16 rows (256B = 16 lanes x uint4)
// lane L: channel-quad cl=L&15; lane-group grp=L>>4 handles neighbors k+grp.
// Direct per-group adjacency reads, HADD2 accumulation, zero-sentinel pad,
// evict_last policy keeps the 51MB gather set L2-resident.
__global__ void __launch_bounds__(256, 8) k_main(int n, float* __restrict__ out,
                                                 double invcnt) {
    unsigned long long pol = mk_evict_last();
    int gtid = blockIdx.x * blockDim.x + threadIdx.x;
    int wid  = gtid >> 5;        // node id
    int lane = gtid & 31;
    int cl   = lane & 15;
    int grp  = lane >> 4;

    float s_local = 0.f;
    if (wid < n) {
        int deg = g_cur[wid];
        if (deg > CAP) deg = CAP;
        if (deg > 0) {
            const int* __restrict__ adj = g_adj + (size_t)wid * CAP;
            const uint4* __restrict__ D = (const uint4*)g_Dh;  // 16 uint4/row
            int degP = (deg + 1) & ~1;
            __half2 h0 = __half2half2(__ushort_as_half(0));
            __half2 h1 = h0, h2 = h0, h3 = h0;
            #pragma unroll 4
            for (int k = grp; k < degP; k += 2) {
                int j = (k < deg) ? ldg_el_i(adj + k, pol) : n;  // n = sentinel
                uint4 x = ldg_el(D + (size_t)j * 16 + cl, pol);
                h0 = __hadd2(h0, *(__half2*)&x.x);
                h1 = __hadd2(h1, *(__half2*)&x.y);
                h2 = __hadd2(h2, *(__half2*)&x.z);
                h3 = __hadd2(h3, *(__half2*)&x.w);
            }
            // combine neighbor-groups (lanes L and L^16 share channels)
            {
                unsigned u0 = *(unsigned*)&h0, u1 = *(unsigned*)&h1;
                unsigned u2 = *(unsigned*)&h2, u3 = *(unsigned*)&h3;
                unsigned v0 = __shfl_xor_sync(0xffffffffu, u0, 16);
                unsigned v1 = __shfl_xor_sync(0xffffffffu, u1, 16);
                unsigned v2 = __shfl_xor_sync(0xffffffffu, u2, 16);
                unsigned v3 = __shfl_xor_sync(0xffffffffu, u3, 16);
                h0 = __hadd2(h0, *(__half2*)&v0);
                h1 = __hadd2(h1, *(__half2*)&v1);
                h2 = __hadd2(h2, *(__half2*)&v2);
                h3 = __hadd2(h3, *(__half2*)&v3);
            }

            uint4 myraw = ldg_el((const uint4*)g_Dh + (size_t)wid * 16 + cl, pol);
            float inv = 1.0f / (float)deg;
            float2 a0 = __half22float2(h0);
            float2 a1 = __half22float2(h1);
            float2 a2 = __half22float2(h2);
            float2 a3 = __half22float2(h3);
            float2 m0 = __half22float2(*(__half2*)&myraw.x);
            float2 m1 = __half22float2(*(__half2*)&myraw.y);
            float2 m2 = __half22float2(*(__half2*)&myraw.z);
            float2 m3 = __half22float2(*(__half2*)&myraw.w);
            s_local = fabsf(m0.x - a0.x * inv) + fabsf(m0.y - a0.y * inv)
                    + fabsf(m1.x - a1.x * inv) + fabsf(m1.y - a1.y * inv)
                    + fabsf(m2.x - a2.x * inv) + fabsf(m2.y - a2.y * inv)
                    + fabsf(m3.x - a3.x * inv) + fabsf(m3.y - a3.y * inv);
            s_local *= 0.5f;   // both lane-groups computed identical terms
        }
    }
    // warp reduce -> per-warp atomic into partial slots
    #pragma unroll
    for (int d = 16; d; d >>= 1)
        s_local += __shfl_xor_sync(0xffffffffu, s_local, d);
    if (lane == 0 && s_local != 0.f)
        atomicAdd(&g_part[blockIdx.x & (NPART - 1)], s_local);

    // ---- epilogue: this block resets its own 8 nodes' counters (coalesced,
    // staggered in time across blocks; no prologue burst — see R5 lesson) ----
    {
        int i = blockIdx.x * 8 + threadIdx.x;
        if (threadIdx.x < 8 && i < n) g_cur[i] = 0;
    }

    // ---- last finishing block reduces the partials, then resets them ----
    __shared__ bool is_last;
    __threadfence();
    if (threadIdx.x == 0)
        is_last = (atomicAdd(&g_done, 1u) == gridDim.x - 1);
    __syncthreads();
    if (is_last) {
        int t = threadIdx.x;                       // 256 threads
        double s = 0.0;
        #pragma unroll
        for (int i = 0; i < NPART / 256; i++) {
            int idx = t + i * 256;
            s += (double)__ldcg(&g_part[idx]);
            g_part[idx] = 0.f;                     // restore for next invocation
        }
        #pragma unroll
        for (int d = 16; d; d >>= 1) s += __shfl_down_sync(0xffffffffu, s, d);
        __shared__ double sh[8];
        if ((t & 31) == 0) sh[t >> 5] = s;
        __syncthreads();
        if (t < 8) {
            double v = sh[t];
            #pragma unroll
            for (int d = 4; d; d >>= 1) v += __shfl_down_sync(0xffu, v, d);
            if (t == 0) {
                out[0] = (float)(v * invcnt);
                g_done = 0u;                       // restore for next invocation
            }
        }
    }
}

extern "C" void kernel_launch(void* const* d_in, const int* in_sizes, int n_in,
                              void* d_out, int out_size) {
    const float* pred = (const float*)d_in[0];
    const float* tgt  = (const float*)d_in[1];
    const int*   esrc = (const int*)d_in[2];
    const int*   edst = (const int*)d_in[3];

    long long total = in_sizes[0];          // B*N*C
    int n = (int)(total / BC);              // 100000
    int e = in_sizes[2];                    // 1600000
    if (n > NMAX) n = NMAX;
    if (e > EMAX) e = EMAX;

    int db = (n * 16 + 255) / 256;          // diff blocks (8 ch/thread)
    int sb = (e + 255) / 256;               // scatter blocks
    k_prep<<<db + sb, 256>>>(pred, tgt, esrc, edst, n, e, db);

    int blocks = (n + 7) / 8;               // 8 warps/block, 1 warp/node
    k_main<<<blocks, 256>>>(n, (float*)d_out, 1.0 / (double)total);
}

// round 14
// speedup vs baseline: 1.0934x; 1.0627x over previous
#include <cuda_runtime.h>
#include <cuda_fp16.h>

// Problem shape (fixed by setup_inputs): B=4, N=100000, C=32, E=1600000
#define NMAX 100000
#define EMAX 1600000
#define NB   4
#define CH   32
#define BC   128            // NB*CH channels per node
#define CAP  64             // fixed adjacency capacity (Poisson(16): P(deg>64)~1e-20)
#define NPART 1024

// Scratch (device globals — zero-initialized at module load; every invocation
// restores them to zero, keeping graph replays deterministic).
// g_Dh has NMAX+1 rows: row NMAX is an all-zero sentinel (never written) used
// to pad gather loops without divergence.
__device__ __half   g_Dh[(size_t)(NMAX + 1) * BC];  // 25.6 MB + 256B sentinel
__device__ int      g_cur[NMAX];                    // per-node fill counter
__device__ int      g_adj[(size_t)NMAX * CAP];      // 25.6 MB fixed-slot adjacency
__device__ float    g_part[NPART];
__device__ unsigned g_done;

// ---------------- fused prep: diff (blocks [0,db)) + scatter (blocks [db,..))
__global__ void __launch_bounds__(256) k_prep(const float* __restrict__ pred,
                                              const float* __restrict__ tgt,
                                              const int* __restrict__ src,
                                              const int* __restrict__ dst,
                                              int n, int e, int db) {
    if ((int)blockIdx.x < db) {
        int t = blockIdx.x * 256 + threadIdx.x;      // 0 .. n*16-1
        if (t >= n * 16) return;
        int node = t >> 4;
        int s    = t & 15;           // uint4 slot in row (8 halves)
        int b    = s >> 2;
        int c    = (s & 3) * 8;
        const float4* P = (const float4*)(pred + (size_t)b * n * CH
                                               + (size_t)node * CH + c);
        const float4* T = (const float4*)(tgt  + (size_t)b * n * CH
                                               + (size_t)node * CH + c);
        float4 p0 = __ldcs(P);
        float4 p1 = __ldcs(P + 1);
        float4 t0 = __ldcs(T);
        float4 t1 = __ldcs(T + 1);
        uint4 o;
        *(__half2*)&o.x = __floats2half2_rn(p0.x - t0.x, p0.y - t0.y);
        *(__half2*)&o.y = __floats2half2_rn(p0.z - t0.z, p0.w - t0.w);
        *(__half2*)&o.z = __floats2half2_rn(p1.x - t1.x, p1.y - t1.y);
        *(__half2*)&o.w = __floats2half2_rn(p1.z - t1.z, p1.w - t1.w);
        ((uint4*)g_Dh)[(size_t)node * 16 + s] = o;
    } else {
        int i = (blockIdx.x - db) * 256 + threadIdx.x;
        if (i < e) {
            int d = __ldcs(dst + i);
            int p = atomicAdd(&g_cur[d], 1);
            if (p < CAP) g_adj[(size_t)d * CAP + p] = __ldcs(src + i);
        }
    }
}

// ---------------- main: 1 warp per node, fp16 rows (256B = 16 lanes x uint4)
// lane L: channel-quad cl=L&15; lane-group grp=L>>4 handles neighbors k+grp.
// Direct per-group adjacency reads, HADD2 accumulation, zero-sentinel pad.
// Launched with Programmatic Dependent Launch: grid comes up while k_prep
// drains; cudaGridDependencySynchronize() gates all memory accesses.
__global__ void __launch_bounds__(256, 8) k_main(int n, float* __restrict__ out,
                                                 double invcnt) {
    int gtid = blockIdx.x * blockDim.x + threadIdx.x;
    int wid  = gtid >> 5;        // node id
    int lane = gtid & 31;
    int cl   = lane & 15;
    int grp  = lane >> 4;

    cudaGridDependencySynchronize();   // PDL: wait for k_prep's writes

    float s_local = 0.f;
    if (wid < n) {
        int deg = g_cur[wid];
        if (deg > CAP) deg = CAP;
        if (deg > 0) {
            const int* __restrict__ adj = g_adj + (size_t)wid * CAP;
            const uint4* __restrict__ D = (const uint4*)g_Dh;  // 16 uint4/row
            int degP = (deg + 1) & ~1;
            __half2 h0 = __half2half2(__ushort_as_half(0));
            __half2 h1 = h0, h2 = h0, h3 = h0;
            #pragma unroll 4
            for (int k = grp; k < degP; k += 2) {
                int j = (k < deg) ? __ldg(adj + k) : n;   // n = zero sentinel
                uint4 x = D[(size_t)j * 16 + cl];
                h0 = __hadd2(h0, *(__half2*)&x.x);
                h1 = __hadd2(h1, *(__half2*)&x.y);
                h2 = __hadd2(h2, *(__half2*)&x.z);
                h3 = __hadd2(h3, *(__half2*)&x.w);
            }
            // combine neighbor-groups (lanes L and L^16 share channels)
            {
                unsigned u0 = *(unsigned*)&h0, u1 = *(unsigned*)&h1;
                unsigned u2 = *(unsigned*)&h2, u3 = *(unsigned*)&h3;
                unsigned v0 = __shfl_xor_sync(0xffffffffu, u0, 16);
                unsigned v1 = __shfl_xor_sync(0xffffffffu, u1, 16);
                unsigned v2 = __shfl_xor_sync(0xffffffffu, u2, 16);
                unsigned v3 = __shfl_xor_sync(0xffffffffu, u3, 16);
                h0 = __hadd2(h0, *(__half2*)&v0);
                h1 = __hadd2(h1, *(__half2*)&v1);
                h2 = __hadd2(h2, *(__half2*)&v2);
                h3 = __hadd2(h3, *(__half2*)&v3);
            }

            uint4 myraw = ((const uint4*)g_Dh)[(size_t)wid * 16 + cl];
            float inv = 1.0f / (float)deg;
            float2 a0 = __half22float2(h0);
            float2 a1 = __half22float2(h1);
            float2 a2 = __half22float2(h2);
            float2 a3 = __half22float2(h3);
            float2 m0 = __half22float2(*(__half2*)&myraw.x);
            float2 m1 = __half22float2(*(__half2*)&myraw.y);
            float2 m2 = __half22float2(*(__half2*)&myraw.z);
            float2 m3 = __half22float2(*(__half2*)&myraw.w);
            s_local = fabsf(m0.x - a0.x * inv) + fabsf(m0.y - a0.y * inv)
                    + fabsf(m1.x - a1.x * inv) + fabsf(m1.y - a1.y * inv)
                    + fabsf(m2.x - a2.x * inv) + fabsf(m2.y - a2.y * inv)
                    + fabsf(m3.x - a3.x * inv) + fabsf(m3.y - a3.y * inv);
            s_local *= 0.5f;   // both lane-groups computed identical terms
        }
    }
    // warp reduce -> per-warp atomic into partial slots
    #pragma unroll
    for (int d = 16; d; d >>= 1)
        s_local += __shfl_xor_sync(0xffffffffu, s_local, d);
    if (lane == 0 && s_local != 0.f)
        atomicAdd(&g_part[blockIdx.x & (NPART - 1)], s_local);

    // ---- epilogue: this block resets its own 8 nodes' counters (coalesced,
    // staggered in time across blocks; no prologue burst — see R5 lesson) ----
    {
        int i = blockIdx.x * 8 + threadIdx.x;
        if (threadIdx.x < 8 && i < n) g_cur[i] = 0;
    }

    // ---- last finishing block reduces the partials, then resets them ----
    __shared__ bool is_last;
    __threadfence();
    if (threadIdx.x == 0)
        is_last = (atomicAdd(&g_done, 1u) == gridDim.x - 1);
    __syncthreads();
    if (is_last) {
        int t = threadIdx.x;                       // 256 threads
        double s = 0.0;
        #pragma unroll
        for (int i = 0; i < NPART / 256; i++) {
            int idx = t + i * 256;
            s += (double)__ldcg(&g_part[idx]);
            g_part[idx] = 0.f;                     // restore for next invocation
        }
        #pragma unroll
        for (int d = 16; d; d >>= 1) s += __shfl_down_sync(0xffffffffu, s, d);
        __shared__ double sh[8];
        if ((t & 31) == 0) sh[t >> 5] = s;
        __syncthreads();
        if (t < 8) {
            double v = sh[t];
            #pragma unroll
            for (int d = 4; d; d >>= 1) v += __shfl_down_sync(0xffu, v, d);
            if (t == 0) {
                out[0] = (float)(v * invcnt);
                g_done = 0u;                       // restore for next invocation
            }
        }
    }
}

extern "C" void kernel_launch(void* const* d_in, const int* in_sizes, int n_in,
                              void* d_out, int out_size) {
    const float* pred = (const float*)d_in[0];
    const float* tgt  = (const float*)d_in[1];
    const int*   esrc = (const int*)d_in[2];
    const int*   edst = (const int*)d_in[3];

    long long total = in_sizes[0];          // B*N*C
    int n = (int)(total / BC);              // 100000
    int e = in_sizes[2];                    // 1600000
    if (n > NMAX) n = NMAX;
    if (e > EMAX) e = EMAX;

    int db = (n * 16 + 255) / 256;          // diff blocks (8 ch/thread)
    int sb = (e + 255) / 256;               // scatter blocks
    k_prep<<<db + sb, 256>>>(pred, tgt, esrc, edst, n, e, db);

    // k_main with Programmatic Dependent Launch: overlaps its launch/setup
    // with k_prep's tail; data dependency enforced by griddepsync in-kernel.
    int blocks = (n + 7) / 8;               // 8 warps/block, 1 warp/node
    float* outp = (float*)d_out;
    double invcnt = 1.0 / (double)total;

    cudaLaunchAttribute attrs[1];
    attrs[0].id = cudaLaunchAttributeProgrammaticStreamSerialization;
    attrs[0].val.programmaticStreamSerializationAllowed = 1;

    cudaLaunchConfig_t cfg = {};
    cfg.gridDim  = dim3(blocks, 1, 1);
    cfg.blockDim = dim3(256, 1, 1);
    cfg.dynamicSmemBytes = 0;
    cfg.stream = 0;
    cfg.attrs = attrs;
    cfg.numAttrs = 1;

    cudaLaunchKernelEx(&cfg, k_main, n, outp, invcnt);
}

// round 15
// speedup vs baseline: 1.1009x; 1.0069x over previous
#include <cuda_runtime.h>
#include <cuda_fp16.h>

// Problem shape (fixed by setup_inputs): B=4, N=100000, C=32, E=1600000
#define NMAX 100000
#define EMAX 1600000
#define NB   4
#define CH   32
#define BC   128            // NB*CH channels per node
#define CAP  64             // fixed adjacency capacity (Poisson(16): P(deg>64)~1e-20)
#define NPART 1024

// Scratch (device globals — zero-initialized at module load; every invocation
// restores them to zero, keeping graph replays deterministic).
// g_Dh has NMAX+1 rows: row NMAX is an all-zero sentinel (never written) used
// to pad gather loops without divergence.
__device__ __half   g_Dh[(size_t)(NMAX + 1) * BC];  // 25.6 MB + 256B sentinel
__device__ int      g_cur[NMAX];                    // per-node fill counter
__device__ int      g_adj[(size_t)NMAX * CAP];      // 25.6 MB fixed-slot adjacency
__device__ float    g_part[NPART];
__device__ unsigned g_done;

// ---------------- fused prep: diff (blocks [0,db)) + scatter (blocks [db,..))
// diff: each thread handles TWO row-slots (s and s+8) of one node ->
// 8 independent LDG.128 in flight + 2 STG.128 (double the streaming MLP of
// the old 1-slot version; issue was only 36% so instruction count is free).
__global__ void __launch_bounds__(256) k_prep(const float* __restrict__ pred,
                                              const float* __restrict__ tgt,
                                              const int* __restrict__ src,
                                              const int* __restrict__ dst,
                                              int n, int e, int db) {
    if ((int)blockIdx.x < db) {
        int t = blockIdx.x * 256 + threadIdx.x;      // 0 .. n*8-1
        if (t >= n * 8) return;
        int node = t >> 3;
        int s0   = t & 7;            // first slot; second is s0+8
        #pragma unroll
        for (int h = 0; h < 2; h++) {
            int s = s0 + h * 8;      // uint4 slot in row (8 halves)
            int b = s >> 2;
            int c = (s & 3) * 8;
            const float4* P = (const float4*)(pred + (size_t)b * n * CH
                                                   + (size_t)node * CH + c);
            const float4* T = (const float4*)(tgt  + (size_t)b * n * CH
                                                   + (size_t)node * CH + c);
            float4 p0 = __ldcs(P);
            float4 p1 = __ldcs(P + 1);
            float4 t0 = __ldcs(T);
            float4 t1 = __ldcs(T + 1);
            uint4 o;
            *(__half2*)&o.x = __floats2half2_rn(p0.x - t0.x, p0.y - t0.y);
            *(__half2*)&o.y = __floats2half2_rn(p0.z - t0.z, p0.w - t0.w);
            *(__half2*)&o.z = __floats2half2_rn(p1.x - t1.x, p1.y - t1.y);
            *(__half2*)&o.w = __floats2half2_rn(p1.z - t1.z, p1.w - t1.w);
            ((uint4*)g_Dh)[(size_t)node * 16 + s] = o;
        }
    } else {
        int i = (blockIdx.x - db) * 256 + threadIdx.x;
        if (i < e) {
            int d = __ldcs(dst + i);
            int p = atomicAdd(&g_cur[d], 1);
            if (p < CAP) g_adj[(size_t)d * CAP + p] = __ldcs(src + i);
        }
    }
}

// ---------------- main (FROZEN at R8 shape + PDL): 1 warp per node, fp16 rows
// (256B = 16 lanes x uint4). lane L: channel-quad cl=L&15; lane-group grp=L>>4
// handles neighbors k+grp. Direct adjacency reads, HADD2, zero-sentinel pad.
__global__ void __launch_bounds__(256, 8) k_main(int n, float* __restrict__ out,
                                                 double invcnt) {
    int gtid = blockIdx.x * blockDim.x + threadIdx.x;
    int wid  = gtid >> 5;        // node id
    int lane = gtid & 31;
    int cl   = lane & 15;
    int grp  = lane >> 4;

    cudaGridDependencySynchronize();   // PDL: wait for k_prep's writes

    float s_local = 0.f;
    if (wid < n) {
        int deg = g_cur[wid];
        if (deg > CAP) deg = CAP;
        if (deg > 0) {
            const int* __restrict__ adj = g_adj + (size_t)wid * CAP;
            const uint4* __restrict__ D = (const uint4*)g_Dh;  // 16 uint4/row
            int degP = (deg + 1) & ~1;
            __half2 h0 = __half2half2(__ushort_as_half(0));
            __half2 h1 = h0, h2 = h0, h3 = h0;
            #pragma unroll 4
            for (int k = grp; k < degP; k += 2) {
                int j = (k < deg) ? __ldg(adj + k) : n;   // n = zero sentinel
                uint4 x = D[(size_t)j * 16 + cl];
                h0 = __hadd2(h0, *(__half2*)&x.x);
                h1 = __hadd2(h1, *(__half2*)&x.y);
                h2 = __hadd2(h2, *(__half2*)&x.z);
                h3 = __hadd2(h3, *(__half2*)&x.w);
            }
            // combine neighbor-groups (lanes L and L^16 share channels)
            {
                unsigned u0 = *(unsigned*)&h0, u1 = *(unsigned*)&h1;
                unsigned u2 = *(unsigned*)&h2, u3 = *(unsigned*)&h3;
                unsigned v0 = __shfl_xor_sync(0xffffffffu, u0, 16);
                unsigned v1 = __shfl_xor_sync(0xffffffffu, u1, 16);
                unsigned v2 = __shfl_xor_sync(0xffffffffu, u2, 16);
                unsigned v3 = __shfl_xor_sync(0xffffffffu, u3, 16);
                h0 = __hadd2(h0, *(__half2*)&v0);
                h1 = __hadd2(h1, *(__half2*)&v1);
                h2 = __hadd2(h2, *(__half2*)&v2);
                h3 = __hadd2(h3, *(__half2*)&v3);
            }

            uint4 myraw = ((const uint4*)g_Dh)[(size_t)wid * 16 + cl];
            float inv = 1.0f / (float)deg;
            float2 a0 = __half22float2(h0);
            float2 a1 = __half22float2(h1);
            float2 a2 = __half22float2(h2);
            float2 a3 = __half22float2(h3);
            float2 m0 = __half22float2(*(__half2*)&myraw.x);
            float2 m1 = __half22float2(*(__half2*)&myraw.y);
            float2 m2 = __half22float2(*(__half2*)&myraw.z);
            float2 m3 = __half22float2(*(__half2*)&myraw.w);
            s_local = fabsf(m0.x - a0.x * inv) + fabsf(m0.y - a0.y * inv)
                    + fabsf(m1.x - a1.x * inv) + fabsf(m1.y - a1.y * inv)
                    + fabsf(m2.x - a2.x * inv) + fabsf(m2.y - a2.y * inv)
                    + fabsf(m3.x - a3.x * inv) + fabsf(m3.y - a3.y * inv);
            s_local *= 0.5f;   // both lane-groups computed identical terms
        }
    }
    // warp reduce -> per-warp atomic into partial slots
    #pragma unroll
    for (int d = 16; d; d >>= 1)
        s_local += __shfl_xor_sync(0xffffffffu, s_local, d);
    if (lane == 0 && s_local != 0.f)
        atomicAdd(&g_part[blockIdx.x & (NPART - 1)], s_local);

    // ---- epilogue: this block resets its own 8 nodes' counters (coalesced,
    // staggered in time across blocks; no prologue burst — see R5 lesson) ----
    {
        int i = blockIdx.x * 8 + threadIdx.x;
        if (threadIdx.x < 8 && i < n) g_cur[i] = 0;
    }

    // ---- last finishing block reduces the partials, then resets them ----
    __shared__ bool is_last;
    __threadfence();
    if (threadIdx.x == 0)
        is_last = (atomicAdd(&g_done, 1u) == gridDim.x - 1);
    __syncthreads();
    if (is_last) {
        int t = threadIdx.x;                       // 256 threads
        double s = 0.0;
        #pragma unroll
        for (int i = 0; i < NPART / 256; i++) {
            int idx = t + i * 256;
            s += (double)__ldcg(&g_part[idx]);
            g_part[idx] = 0.f;                     // restore for next invocation
        }
        #pragma unroll
        for (int d = 16; d; d >>= 1) s += __shfl_down_sync(0xffffffffu, s, d);
        __shared__ double sh[8];
        if ((t & 31) == 0) sh[t >> 5] = s;
        __syncthreads();
        if (t < 8) {
            double v = sh[t];
            #pragma unroll
            for (int d = 4; d; d >>= 1) v += __shfl_down_sync(0xffu, v, d);
            if (t == 0) {
                out[0] = (float)(v * invcnt);
                g_done = 0u;                       // restore for next invocation
            }
        }
    }
}

extern "C" void kernel_launch(void* const* d_in, const int* in_sizes, int n_in,
                              void* d_out, int out_size) {
    const float* pred = (const float*)d_in[0];
    const float* tgt  = (const float*)d_in[1];
    const int*   esrc = (const int*)d_in[2];
    const int*   edst = (const int*)d_in[3];

    long long total = in_sizes[0];          // B*N*C
    int n = (int)(total / BC);              // 100000
    int e = in_sizes[2];                    // 1600000
    if (n > NMAX) n = NMAX;
    if (e > EMAX) e = EMAX;

    int db = (n * 8 + 255) / 256;           // diff blocks (16 ch x 2 slots/thread)
    int sb = (e + 255) / 256;               // scatter blocks
    k_prep<<<db + sb, 256>>>(pred, tgt, esrc, edst, n, e, db);

    // k_main with Programmatic Dependent Launch: overlaps its launch/setup
    // with k_prep's tail; data dependency enforced by griddepsync in-kernel.
    int blocks = (n + 7) / 8;               // 8 warps/block, 1 warp/node
    float* outp = (float*)d_out;
    double invcnt = 1.0 / (double)total;

    cudaLaunchAttribute attrs[1];
    attrs[0].id = cudaLaunchAttributeProgrammaticStreamSerialization;
    attrs[0].val.programmaticStreamSerializationAllowed = 1;

    cudaLaunchConfig_t cfg = {};
    cfg.gridDim  = dim3(blocks, 1, 1);
    cfg.blockDim = dim3(256, 1, 1);
    cfg.dynamicSmemBytes = 0;
    cfg.stream = 0;
    cfg.attrs = attrs;
    cfg.numAttrs = 1;

    cudaLaunchKernelEx(&cfg, k_main, n, outp, invcnt);
}